// round 2
// baseline (speedup 1.0000x reference)
#include <cuda_runtime.h>
#include <cstdint>

// ---------------------------------------------------------------------------
// BaseGCN split into two kernels:
//   A) gcn_knn:   per row, find k nearest neighbor indices -> g_knn scratch.
//   B) gcn_write: per row, stream the 16KB output row from a 4096-bit bitmap.
// out[g,i,j] = (j==i) - (1/k) * [j in knn(i)]   (deg == k always).
// ---------------------------------------------------------------------------

constexpr int NN   = 4096;
constexpr int ROWS = 8;       // rows per CTA in kernel A (== warps per CTA)
constexpr int NT   = 256;
constexpr int CPT  = NN / NT; // 16 candidates per thread
constexpr int CAP  = 128;     // candidate buffer per row
constexpr int MAXROWS = 4 * NN;   // 16384

__device__ int g_knn[MAXROWS * 32];   // 2 MB scratch: knn indices (-1 padded)

// dynamic smem layout for kernel A (bytes)
constexpr int SMEM_PTS  = 0;                  // float4 sp[4096]  = 65536
constexpr int SMEM_OVL  = 65536;              // tmin[8][256] f32 OR cand[8][128] u64
constexpr int SMEM_KNN  = SMEM_OVL + 8192;    // int knn[8][32]
constexpr int SMEM_MISC = SMEM_KNN + 1024;
constexpr int SMEM_TOTAL = SMEM_MISC + 256;   // 75264 B

__device__ __forceinline__ unsigned f2ord(float f) {
    unsigned b = __float_as_uint(f);
    return b ^ ((b & 0x80000000u) ? 0xFFFFFFFFu : 0x80000000u);
}
__device__ __forceinline__ float ord2f(unsigned u) {
    unsigned b = (u & 0x80000000u) ? (u ^ 0x80000000u) : ~u;
    return __uint_as_float(b);
}

// ========================== Kernel A: kNN ==================================
extern "C" __global__ void __launch_bounds__(NT, 3)
gcn_knn(const float* __restrict__ x, const int* __restrict__ kptr) {
    extern __shared__ unsigned char smem_raw[];
    float4* sp = reinterpret_cast<float4*>(smem_raw + SMEM_PTS);
    float (*tmin)[NT] = reinterpret_cast<float(*)[NT]>(smem_raw + SMEM_OVL);
    unsigned long long (*cand)[CAP] =
        reinterpret_cast<unsigned long long(*)[CAP]>(smem_raw + SMEM_OVL);
    int (*knn)[32] = reinterpret_cast<int(*)[32]>(smem_raw + SMEM_KNN);
    int*      cnt        = reinterpret_cast<int*>(smem_raw + SMEM_MISC);
    unsigned* tbits      = reinterpret_cast<unsigned*>(smem_raw + SMEM_MISC + 32);
    int*      active     = reinterpret_cast<int*>(smem_raw + SMEM_MISC + 64);
    int*      active_any = reinterpret_cast<int*>(smem_raw + SMEM_MISC + 96);

    const int tid   = threadIdx.x;
    const int lane  = tid & 31;
    const int w     = tid >> 5;
    const int row0  = blockIdx.x * ROWS;
    const int batch = row0 >> 12;
    const int i0    = row0 & (NN - 1);
    const float* xb = x + (size_t)batch * NN * 3;

    int kk = (kptr != nullptr) ? *kptr : 20;
    kk = max(1, min(kk, 32));

    // stage points: float4 {x, y, z, |x|^2}
    for (int p = tid; p < NN; p += NT) {
        float a = xb[3 * p], b = xb[3 * p + 1], c = xb[3 * p + 2];
        sp[p] = make_float4(a, b, c, fmaf(a, a, fmaf(b, b, c * c)));
    }
    __syncthreads();

    float m2x[ROWS], m2y[ROWS], m2z[ROWS];
#pragma unroll
    for (int r = 0; r < ROWS; ++r) {
        float4 q = sp[i0 + r];
        m2x[r] = -2.0f * q.x; m2y[r] = -2.0f * q.y; m2z[r] = -2.0f * q.z;
    }

    // pass 1: per-thread minima of shifted key s = |x_j|^2 - 2 x_i.x_j
    float tm[ROWS];
#pragma unroll
    for (int r = 0; r < ROWS; ++r) tm[r] = 3.0e38f;
    for (int t = 0; t < CPT; ++t) {
        float4 c = sp[t * NT + tid];
#pragma unroll
        for (int r = 0; r < ROWS; ++r) {
            float s = fmaf(c.x, m2x[r], fmaf(c.y, m2y[r], fmaf(c.z, m2z[r], c.w)));
            tm[r] = fminf(tm[r], s);
        }
    }
#pragma unroll
    for (int r = 0; r < ROWS; ++r) tmin[r][tid] = tm[r];
    __syncthreads();

    // phase 2: warp w -> row w; rank-(kk+4) of 256 minima via bit bisection.
    // Guarantee: >= kk+4 values lie <= T, and {v <= T} is downward closed,
    // so the true top-k is always contained in the collected set.
    {
        unsigned vb[8];
#pragma unroll
        for (int s = 0; s < 8; ++s) vb[s] = f2ord(tmin[w][lane * 8 + s]);
        const int rank = kk + 4;
        unsigned lo = 0u, hi = 0xFFFFFFFFu;
#pragma unroll 1
        for (int it = 0; it < 32 && lo < hi; ++it) {
            unsigned mid = lo + ((hi - lo) >> 1);
            int cle = 0;
#pragma unroll
            for (int s = 0; s < 8; ++s) cle += (vb[s] <= mid) ? 1 : 0;
            cle = __reduce_add_sync(0xFFFFFFFFu, cle);
            if (cle >= rank) hi = mid; else lo = mid + 1;
        }
        if (lane == 0) { tbits[w] = lo; cnt[w] = 0; active[w] = 1; }
    }
    __syncthreads();

    // phase 3: collect candidates <= threshold (retry statistically unreachable)
    for (int attempt = 0; attempt < 4; ++attempt) {
        if (tid == 0) {
            int any = 0;
#pragma unroll
            for (int r = 0; r < ROWS; ++r) any |= active[r];
            *active_any = any;
        }
        __syncthreads();
        if (!*active_any) break;
        float thr[ROWS]; int act[ROWS];
#pragma unroll
        for (int r = 0; r < ROWS; ++r) { thr[r] = ord2f(tbits[r]); act[r] = active[r]; }
        for (int t = 0; t < CPT; ++t) {
            int j = t * NT + tid;
            float4 c = sp[j];
#pragma unroll
            for (int r = 0; r < ROWS; ++r) {
                if (!act[r]) continue;
                float s = fmaf(c.x, m2x[r], fmaf(c.y, m2y[r], fmaf(c.z, m2z[r], c.w)));
                if (s <= thr[r]) {
                    int pos = atomicAdd(&cnt[r], 1);
                    if (pos < CAP)
                        cand[r][pos] =
                            ((unsigned long long)f2ord(s) << 32) | (unsigned)j;
                }
            }
        }
        __syncthreads();
        if (tid < ROWS) {
            if (active[tid]) {
                if (cnt[tid] >= kk) {
                    active[tid] = 0;
                } else {
                    unsigned tb = tbits[tid];
                    tb = (tb > 0xFF000000u) ? 0xFF7FFFFFu : tb + 0x00800000u;
                    tbits[tid] = tb; cnt[tid] = 0;
                }
            }
        }
        __syncthreads();
    }

    // phase 4: warp w ranks its <=CAP candidates by counting (no serial
    // reductions). 64-bit keys (ordered dist, index) are distinct -> ranks
    // are a permutation; rank < kk selects top-k with lowest-index ties.
    {
        const int r = w;
        const int c = min(cnt[r], CAP);
        unsigned long long my[4];
#pragma unroll
        for (int s = 0; s < 4; ++s) {
            int pos = lane + 32 * s;
            my[s] = (pos < c) ? cand[r][pos] : ~0ull;
        }
        int rk[4] = {0, 0, 0, 0};
#pragma unroll 4
        for (int s = 0; s < c; ++s) {
            unsigned long long kc = cand[r][s];   // LDS broadcast
#pragma unroll
            for (int m = 0; m < 4; ++m) rk[m] += (kc < my[m]) ? 1 : 0;
        }
        knn[r][lane] = -1;
        __syncwarp();
#pragma unroll
        for (int m = 0; m < 4; ++m)
            if (my[m] != ~0ull && rk[m] < kk)
                knn[r][rk[m]] = (int)(unsigned)my[m];
        __syncwarp();
        g_knn[(size_t)(row0 + r) * 32 + lane] = knn[r][lane];
    }
}

// ========================== Kernel B: row writer ===========================
extern "C" __global__ void __launch_bounds__(NT)
gcn_write(const int* __restrict__ kptr, float* __restrict__ out) {
    __shared__ unsigned bm[NN / 32];    // 4096-bit membership bitmap (512 B)

    const int tid  = threadIdx.x;
    const int row  = blockIdx.x;
    const int iloc = row & (NN - 1);

    int kk = (kptr != nullptr) ? *kptr : 20;
    kk = max(1, min(kk, 32));
    const float voff = -1.0f / (float)kk;

    if (tid < NN / 32) bm[tid] = 0u;
    __syncthreads();
    if (tid < 32) {
        int j = g_knn[(size_t)row * 32 + tid];
        if (tid < kk && j >= 0) atomicOr(&bm[j >> 5], 1u << (j & 31));
    }
    __syncthreads();

    float4* out4 = reinterpret_cast<float4*>(out) + (size_t)row * (NN / 4);
    const int dm = iloc >> 2;        // float4 index containing the diagonal
#pragma unroll
    for (int it = 0; it < 4; ++it) {
        int m = tid + it * NT;                       // float4 index 0..1023
        unsigned nib = (bm[m >> 3] >> ((m & 7) * 4)) & 15u;
        float4 v;
        v.x = (nib & 1u) ? voff : 0.0f;
        v.y = (nib & 2u) ? voff : 0.0f;
        v.z = (nib & 4u) ? voff : 0.0f;
        v.w = (nib & 8u) ? voff : 0.0f;
        if (m == dm) {
            int c = iloc & 3;
            if (c == 0) v.x += 1.0f; else if (c == 1) v.y += 1.0f;
            else if (c == 2) v.z += 1.0f; else v.w += 1.0f;
        }
        out4[m] = v;
    }
}

// ========================== launch =========================================
extern "C" void kernel_launch(void* const* d_in, const int* in_sizes, int n_in,
                              void* d_out, int out_size) {
    const float* x   = (const float*)d_in[0];
    const int*   kpt = (n_in >= 2) ? (const int*)d_in[1] : nullptr;
    float*       out = (float*)d_out;

    int total_rows = in_sizes[0] / 3;           // B * N = 16384
    int gridA = total_rows / ROWS;              // 2048

    cudaFuncSetAttribute(gcn_knn,
                         cudaFuncAttributeMaxDynamicSharedMemorySize, SMEM_TOTAL);
    gcn_knn<<<gridA, NT, SMEM_TOTAL>>>(x, kpt);
    gcn_write<<<total_rows, NT>>>(kpt, out);
}

// round 3
// speedup vs baseline: 1.3062x; 1.3062x over previous
#include <cuda_runtime.h>
#include <cstdint>

// ---------------------------------------------------------------------------
// BaseGCN fused kernel: kNN selection + Laplacian row write, one CTA = 8 rows.
// out[g,i,j] = (j==i) - (1/k) * [j in knn(i)]   (deg == k always).
//
// Per CTA (256 thr, one batch):
//  stage xs/ys/zs (48KB smem)
//  pass1: per-thread minima of s_j = |x_j|^2 - 2 x_i.x_j for 8 rows,
//         reduced to 32 group-of-8 minima, stored as u16 ordered prefixes
//  phase2: warp w = row w: counting-rank of 32 minima -> threshold T
//          (rank k+3 guarantees >= k+4 candidates <= T, deterministic)
//  pass3: recompute s, collect (ord(s),j) keys <= T into cand[row][<=96]
//  phase4: counting-rank of candidates -> knn indices (lowest-index ties,
//          matching lax.top_k)
//  write:  warp w streams its 16KB row from a 4xu32 register nibble-bitmap
// ---------------------------------------------------------------------------

constexpr int NN   = 4096;
constexpr int ROWS = 8;
constexpr int NT   = 256;
constexpr int CPT  = NN / NT;  // 16
constexpr int CAP  = 96;

// smem offsets (bytes)
constexpr int OFF_X    = 0;                       // float xs[4096]
constexpr int OFF_Y    = 16384;                   // float ys[4096]
constexpr int OFF_Z    = 32768;                   // float zs[4096]
constexpr int OFF_TM   = 49152;                   // u16 tm16[8][32]   512B
constexpr int OFF_CAND = 49664;                   // u64 cand[8][96]  6144B
constexpr int OFF_KNN  = 55808;                   // int knn[8][32]   1024B
constexpr int OFF_MISC = 56832;                   // sT16[8], cnt[8], act[8], any
constexpr int SMEM_TOTAL = OFF_MISC + 128;        // 56960B -> 4 CTAs/SM

__device__ __forceinline__ unsigned f2ord(float f) {
    unsigned b = __float_as_uint(f);
    return b ^ ((b & 0x80000000u) ? 0xFFFFFFFFu : 0x80000000u);
}
__device__ __forceinline__ float ord2f(unsigned u) {
    unsigned b = (u & 0x80000000u) ? (u ^ 0x80000000u) : ~u;
    return __uint_as_float(b);
}

extern "C" __global__ void __launch_bounds__(NT, 4)
gcn_fused(const float* __restrict__ x, const int* __restrict__ kptr,
          float* __restrict__ out) {
    extern __shared__ unsigned char sm[];
    float* xs = reinterpret_cast<float*>(sm + OFF_X);
    float* ys = reinterpret_cast<float*>(sm + OFF_Y);
    float* zs = reinterpret_cast<float*>(sm + OFF_Z);
    unsigned short (*tm16)[32] =
        reinterpret_cast<unsigned short(*)[32]>(sm + OFF_TM);
    unsigned long long (*cand)[CAP] =
        reinterpret_cast<unsigned long long(*)[CAP]>(sm + OFF_CAND);
    int (*knn)[32] = reinterpret_cast<int(*)[32]>(sm + OFF_KNN);
    unsigned* sT16 = reinterpret_cast<unsigned*>(sm + OFF_MISC);
    int*      cnt  = reinterpret_cast<int*>(sm + OFF_MISC + 32);
    int*      act  = reinterpret_cast<int*>(sm + OFF_MISC + 64);
    int*      anyf = reinterpret_cast<int*>(sm + OFF_MISC + 96);

    const int tid   = threadIdx.x;
    const int lane  = tid & 31;
    const int w     = tid >> 5;
    const int row0  = blockIdx.x * ROWS;
    const int batch = row0 >> 12;
    const int i0    = row0 & (NN - 1);
    const float* xb = x + (size_t)batch * NN * 3;

    int kk = (kptr != nullptr) ? *kptr : 20;
    kk = max(1, min(kk, 28));

    // ---- stage points ----
    for (int p = tid; p < NN; p += NT) {
        xs[p] = xb[3 * p]; ys[p] = xb[3 * p + 1]; zs[p] = xb[3 * p + 2];
    }
    __syncthreads();

    float m2x[ROWS], m2y[ROWS], m2z[ROWS];
#pragma unroll
    for (int r = 0; r < ROWS; ++r) {
        m2x[r] = -2.0f * xs[i0 + r];
        m2y[r] = -2.0f * ys[i0 + r];
        m2z[r] = -2.0f * zs[i0 + r];
    }

    // ---- pass 1: per-thread minima; reduce groups of 8 -> u16 prefixes ----
    float tm[ROWS];
#pragma unroll
    for (int r = 0; r < ROWS; ++r) tm[r] = 3.0e38f;
#pragma unroll 4
    for (int t = 0; t < CPT; ++t) {
        int j = t * NT + tid;
        float cx = xs[j], cy = ys[j], cz = zs[j];
        float cw = fmaf(cx, cx, fmaf(cy, cy, cz * cz));
#pragma unroll
        for (int r = 0; r < ROWS; ++r) {
            float s = fmaf(cx, m2x[r], fmaf(cy, m2y[r], fmaf(cz, m2z[r], cw)));
            tm[r] = fminf(tm[r], s);
        }
    }
#pragma unroll
    for (int r = 0; r < ROWS; ++r) {
        float v = tm[r];
        v = fminf(v, __shfl_down_sync(0xFFFFFFFFu, v, 4, 8));
        v = fminf(v, __shfl_down_sync(0xFFFFFFFFu, v, 2, 8));
        v = fminf(v, __shfl_down_sync(0xFFFFFFFFu, v, 1, 8));
        if ((tid & 7) == 0)
            tm16[r][tid >> 3] = (unsigned short)(f2ord(v) >> 16);
    }
    if (tid < ROWS) act[tid] = 1;
    __syncthreads();

    const unsigned lm = (unsigned)tm16[w][lane];  // warp w owns row w

    // ---- attempts: rank kk+3 (guarantee >= kk+4), fallback rank kk-1 ----
    for (int attempt = 0; attempt < 2; ++attempt) {
        if (act[w]) {
            const int rank0 = (attempt == 0) ? (kk + 3) : (kk - 1);
            int c = 0;
#pragma unroll
            for (int s = 0; s < 32; ++s) {
                unsigned v = __shfl_sync(0xFFFFFFFFu, lm, s);
                c += (v < lm || (v == lm && s < lane)) ? 1 : 0;
            }
            unsigned eq = __ballot_sync(0xFFFFFFFFu, c == rank0);
            unsigned T16 = __shfl_sync(0xFFFFFFFFu, lm, __ffs(eq) - 1);
            if (lane == 0) { sT16[w] = T16; cnt[w] = 0; }
        }
        __syncthreads();

        float thrf[ROWS];
#pragma unroll
        for (int r = 0; r < ROWS; ++r)
            thrf[r] = act[r] ? ord2f((sT16[r] << 16) | 0xFFFFu)
                             : __int_as_float(0xFF800000);  // -inf

        // ---- pass 3: collect candidates <= per-row threshold ----
#pragma unroll 2
        for (int t = 0; t < CPT; ++t) {
            int j = t * NT + tid;
            float cx = xs[j], cy = ys[j], cz = zs[j];
            float cw = fmaf(cx, cx, fmaf(cy, cy, cz * cz));
#pragma unroll
            for (int r = 0; r < ROWS; ++r) {
                float s = fmaf(cx, m2x[r], fmaf(cy, m2y[r], fmaf(cz, m2z[r], cw)));
                if (s <= thrf[r]) {
                    int pos = atomicAdd(&cnt[r], 1);
                    if (pos < CAP)
                        cand[r][pos] =
                            ((unsigned long long)f2ord(s) << 32) | (unsigned)j;
                }
            }
        }
        __syncthreads();
        if (tid < ROWS) {
            if (act[tid]) act[tid] = (cnt[tid] > CAP) ? 1 : 0;
        }
        if (tid == 0) {
            int a = 0;
#pragma unroll
            for (int r = 0; r < ROWS; ++r) a |= act[r];
            *anyf = a;
        }
        __syncthreads();
        if (!*anyf) break;
    }

    // ---- phase 4: rank candidates of row w by counting ----
    {
        const int c = min(cnt[w], CAP);
        unsigned long long my[3];
#pragma unroll
        for (int m = 0; m < 3; ++m) {
            int pos = lane + 32 * m;
            my[m] = (pos < c) ? cand[w][pos] : ~0ull;
        }
        int rk[3] = {0, 0, 0};
#pragma unroll 4
        for (int s = 0; s < c; ++s) {
            unsigned long long kc = cand[w][s];
#pragma unroll
            for (int m = 0; m < 3; ++m) rk[m] += (kc < my[m]) ? 1 : 0;
        }
        knn[w][lane] = -1;
        __syncwarp();
#pragma unroll
        for (int m = 0; m < 3; ++m)
            if (my[m] != ~0ull && rk[m] < kk)
                knn[w][rk[m]] = (int)(unsigned)my[m];
        __syncwarp();
    }

    // ---- write phase: warp w streams row (row0 + w) ----
    {
        const int grow = row0 + w;
        const int iloc = i0 + w;
        const float voff = -1.0f / (float)kk;

        // register nibble-bitmap: lane covers float4 groups m = lane + 32*it
        unsigned b0 = 0, b1 = 0, b2 = 0, b3 = 0;
        for (int q = 0; q < kk; ++q) {
            int j = knn[w][q];
            if (j >= 0 && ((j >> 2) & 31) == lane) {
                int it = j >> 7;
                unsigned sh = 1u << (((it & 7) << 2) | (j & 3));
                if (it < 8) b0 |= sh; else if (it < 16) b1 |= sh;
                else if (it < 24) b2 |= sh; else b3 |= sh;
            }
        }

        float4* ob = reinterpret_cast<float4*>(out) + (size_t)grow * (NN / 4) + lane;
#pragma unroll
        for (int it = 0; it < 32; ++it) {
            unsigned reg = (it < 8) ? b0 : (it < 16) ? b1 : (it < 24) ? b2 : b3;
            unsigned nib = (reg >> ((it & 7) * 4)) & 15u;
            float4 v;
            v.x = (nib & 1u) ? voff : 0.0f;
            v.y = (nib & 2u) ? voff : 0.0f;
            v.z = (nib & 4u) ? voff : 0.0f;
            v.w = (nib & 8u) ? voff : 0.0f;
            ob[it * 32] = v;
        }
        // diagonal: same thread that wrote the containing float4 -> ordered
        const int dl = (iloc >> 2) & 31;
        if (lane == dl) {
            const int dit = iloc >> 7;
            unsigned reg = (dit < 8) ? b0 : (dit < 16) ? b1 : (dit < 24) ? b2 : b3;
            unsigned bit = (reg >> (((dit & 7) << 2) | (iloc & 3))) & 1u;
            out[(size_t)grow * NN + iloc] = 1.0f + (bit ? voff : 0.0f);
        }
    }
}

extern "C" void kernel_launch(void* const* d_in, const int* in_sizes, int n_in,
                              void* d_out, int out_size) {
    const float* x   = (const float*)d_in[0];
    const int*   kpt = (n_in >= 2) ? (const int*)d_in[1] : nullptr;
    float*       out = (float*)d_out;

    int total_rows = in_sizes[0] / 3;      // 16384
    int grid = total_rows / ROWS;          // 2048

    cudaFuncSetAttribute(gcn_fused,
                         cudaFuncAttributeMaxDynamicSharedMemorySize, SMEM_TOTAL);
    gcn_fused<<<grid, NT, SMEM_TOTAL>>>(x, kpt, out);
}

// round 4
// speedup vs baseline: 1.4246x; 1.0907x over previous
#include <cuda_runtime.h>
#include <cstdint>

// ---------------------------------------------------------------------------
// BaseGCN fused: kNN selection + Laplacian row write. One CTA = 8 rows.
// out[g,i,j] = (j==i) - (1/k) * [j in knn(i)]   (deg == k always).
//
//  stage xs/ys/zs (48KB) + 16-entry nibble->float4 LUT
//  pass1: per-thread minima over 16 candidates (float2 groups) for 8 rows,
//         reduced to 32 group-of-8 minima as u16 ordered prefixes
//  threshold: warp w (row w) counting-ranks the 32 minima; rank k-1 value T
//         guarantees >= k candidates <= T (the k group minima themselves),
//         so collected set provably contains the top-k.
//  pass3: recompute s, __any_sync-gated collection of keys <= T (E ~ 23)
//  phase4: counting-rank of candidates -> exact top-k, lowest-index ties
//         (64-bit (ord(dist), idx) keys match lax.top_k ordering)
//  write: warp w streams its 16KB row: nibble bitmap -> LUT -> STG.128
// ---------------------------------------------------------------------------

constexpr int NN   = 4096;
constexpr int ROWS = 8;
constexpr int NT   = 256;
constexpr int CAP  = 64;

// smem offsets (bytes)
constexpr int OFF_X    = 0;          // float xs[4096]
constexpr int OFF_Y    = 16384;      // float ys[4096]
constexpr int OFF_Z    = 32768;      // float zs[4096]
constexpr int OFF_TM   = 49152;      // u16 tm16[8][32]      512
constexpr int OFF_CAND = 49664;      // u64 cand[8][64]     4096
constexpr int OFF_KNN  = 53760;      // int knn[8][32]      1024
constexpr int OFF_LUT  = 54784;      // float4 lut[16]       256
constexpr int OFF_MISC = 55040;      // sT16[8] cnt[8] act[8] anyf
constexpr int SMEM_TOTAL = OFF_MISC + 128;   // 55168 -> 4 CTAs/SM

__device__ __forceinline__ unsigned f2ord(float f) {
    unsigned b = __float_as_uint(f);
    return b ^ ((b & 0x80000000u) ? 0xFFFFFFFFu : 0x80000000u);
}
__device__ __forceinline__ float ord2f(unsigned u) {
    unsigned b = (u & 0x80000000u) ? (u ^ 0x80000000u) : ~u;
    return __uint_as_float(b);
}

extern "C" __global__ void __launch_bounds__(NT, 4)
gcn_fused(const float* __restrict__ x, const int* __restrict__ kptr,
          float* __restrict__ out) {
    extern __shared__ unsigned char sm[];
    float* xs = reinterpret_cast<float*>(sm + OFF_X);
    float* ys = reinterpret_cast<float*>(sm + OFF_Y);
    float* zs = reinterpret_cast<float*>(sm + OFF_Z);
    unsigned short (*tm16)[32] =
        reinterpret_cast<unsigned short(*)[32]>(sm + OFF_TM);
    unsigned long long (*cand)[CAP] =
        reinterpret_cast<unsigned long long(*)[CAP]>(sm + OFF_CAND);
    int (*knn)[32] = reinterpret_cast<int(*)[32]>(sm + OFF_KNN);
    float4*   lut  = reinterpret_cast<float4*>(sm + OFF_LUT);
    unsigned* sT16 = reinterpret_cast<unsigned*>(sm + OFF_MISC);
    int*      cnt  = reinterpret_cast<int*>(sm + OFF_MISC + 32);
    int*      act  = reinterpret_cast<int*>(sm + OFF_MISC + 64);
    int*      anyf = reinterpret_cast<int*>(sm + OFF_MISC + 96);

    const int tid   = threadIdx.x;
    const int lane  = tid & 31;
    const int w     = tid >> 5;
    const int row0  = blockIdx.x * ROWS;
    const int batch = row0 >> 12;
    const int i0    = row0 & (NN - 1);
    const float* xb = x + (size_t)batch * NN * 3;

    int kk = (kptr != nullptr) ? *kptr : 20;
    kk = max(1, min(kk, 32));
    const float voff = -1.0f / (float)kk;

    // ---- stage points + LUT ----
    for (int p = tid; p < NN; p += NT) {
        xs[p] = xb[3 * p]; ys[p] = xb[3 * p + 1]; zs[p] = xb[3 * p + 2];
    }
    if (tid < 16) {
        float4 v;
        v.x = (tid & 1) ? voff : 0.0f;
        v.y = (tid & 2) ? voff : 0.0f;
        v.z = (tid & 4) ? voff : 0.0f;
        v.w = (tid & 8) ? voff : 0.0f;
        lut[tid] = v;
    }
    if (tid < ROWS) act[tid] = 1;
    __syncthreads();

    float m2x[ROWS], m2y[ROWS], m2z[ROWS];
#pragma unroll
    for (int r = 0; r < ROWS; ++r) {
        m2x[r] = -2.0f * xs[i0 + r];
        m2y[r] = -2.0f * ys[i0 + r];
        m2z[r] = -2.0f * zs[i0 + r];
    }

    const float2* xs2 = reinterpret_cast<const float2*>(xs);
    const float2* ys2 = reinterpret_cast<const float2*>(ys);
    const float2* zs2 = reinterpret_cast<const float2*>(zs);

    // ---- pass 1: per-thread minima over 8 float2 groups (16 candidates) ----
    float tm[ROWS];
#pragma unroll
    for (int r = 0; r < ROWS; ++r) tm[r] = 3.0e38f;
#pragma unroll 2
    for (int t = 0; t < 8; ++t) {
        int g = t * 256 + tid;               // float2 index; j = 2g, 2g+1
        float2 cx = xs2[g], cy = ys2[g], cz = zs2[g];
        float cw0 = fmaf(cx.x, cx.x, fmaf(cy.x, cy.x, cz.x * cz.x));
        float cw1 = fmaf(cx.y, cx.y, fmaf(cy.y, cy.y, cz.y * cz.y));
#pragma unroll
        for (int r = 0; r < ROWS; ++r) {
            float s0 = fmaf(cx.x, m2x[r], fmaf(cy.x, m2y[r], fmaf(cz.x, m2z[r], cw0)));
            float s1 = fmaf(cx.y, m2x[r], fmaf(cy.y, m2y[r], fmaf(cz.y, m2z[r], cw1)));
            tm[r] = fminf(tm[r], fminf(s0, s1));
        }
    }
    // group-of-8 minima -> u16 ordered prefixes (32 groups; group covers 128
    // distinct candidates: tid in [8g,8g+8), t in [0,8), j = 1024t + 2tid + {0,1})
#pragma unroll
    for (int r = 0; r < ROWS; ++r) {
        float v = tm[r];
        v = fminf(v, __shfl_down_sync(0xFFFFFFFFu, v, 4, 8));
        v = fminf(v, __shfl_down_sync(0xFFFFFFFFu, v, 2, 8));
        v = fminf(v, __shfl_down_sync(0xFFFFFFFFu, v, 1, 8));
        if ((tid & 7) == 0)
            tm16[r][tid >> 3] = (unsigned short)(f2ord(v) >> 16);
    }
    __syncthreads();

    // ---- threshold: lex counting-rank (kk-1) of the 32 group minima ----
    unsigned T16base;
    {
        const unsigned lm = (unsigned)tm16[w][lane];
        int c = 0;
#pragma unroll
        for (int s = 0; s < 32; ++s) {
            unsigned v = __shfl_sync(0xFFFFFFFFu, lm, s);
            c += (v < lm || (v == lm && s < lane)) ? 1 : 0;
        }
        unsigned eq = __ballot_sync(0xFFFFFFFFu, c == kk - 1);
        T16base = __shfl_sync(0xFFFFFFFFu, lm, __ffs(eq) - 1);
    }

    // ---- collection attempts (attempt > 0 statistically unreachable) ----
    for (int attempt = 0; attempt < 3; ++attempt) {
        if (lane == 0 && act[w]) {
            unsigned d = (unsigned)attempt;
            sT16[w] = (T16base > d) ? (T16base - d) : 0u;
            cnt[w] = 0;
        }
        __syncthreads();

        float thrf[ROWS];
#pragma unroll
        for (int r = 0; r < ROWS; ++r)
            thrf[r] = act[r] ? ord2f((sT16[r] << 16) | 0xFFFFu)
                             : __int_as_float(0xFF800000);   // -inf

        // pass 3: recompute s, collect keys <= T (any_sync-gated)
#pragma unroll 2
        for (int t = 0; t < 8; ++t) {
            int g = t * 256 + tid;
            int j0 = 2 * g;
            float2 cx = xs2[g], cy = ys2[g], cz = zs2[g];
            float cw0 = fmaf(cx.x, cx.x, fmaf(cy.x, cy.x, cz.x * cz.x));
            float cw1 = fmaf(cx.y, cx.y, fmaf(cy.y, cy.y, cz.y * cz.y));
#pragma unroll
            for (int r = 0; r < ROWS; ++r) {
                float s0 = fmaf(cx.x, m2x[r], fmaf(cy.x, m2y[r], fmaf(cz.x, m2z[r], cw0)));
                float s1 = fmaf(cx.y, m2x[r], fmaf(cy.y, m2y[r], fmaf(cz.y, m2z[r], cw1)));
                bool hit = fminf(s0, s1) <= thrf[r];
                if (__any_sync(0xFFFFFFFFu, hit)) {
                    if (s0 <= thrf[r]) {
                        int pos = atomicAdd(&cnt[r], 1);
                        if (pos < CAP)
                            cand[r][pos] =
                                ((unsigned long long)f2ord(s0) << 32) | (unsigned)j0;
                    }
                    if (s1 <= thrf[r]) {
                        int pos = atomicAdd(&cnt[r], 1);
                        if (pos < CAP)
                            cand[r][pos] =
                                ((unsigned long long)f2ord(s1) << 32) | (unsigned)(j0 + 1);
                    }
                }
            }
        }
        __syncthreads();
        if (tid < ROWS) {
            if (act[tid]) act[tid] = (cnt[tid] > CAP) ? 1 : 0;
        }
        if (tid == 0) {
            int a = 0;
#pragma unroll
            for (int r = 0; r < ROWS; ++r) a |= act[r];
            *anyf = a;
        }
        __syncthreads();
        if (!*anyf) break;
    }

    // ---- phase 4: counting-rank candidates of row w (exact top-k) ----
    {
        const int c = min(cnt[w], CAP);
        unsigned long long my[2];
#pragma unroll
        for (int m = 0; m < 2; ++m) {
            int pos = lane + 32 * m;
            my[m] = (pos < c) ? cand[w][pos] : ~0ull;
        }
        int rk[2] = {0, 0};
#pragma unroll 4
        for (int s = 0; s < c; ++s) {
            unsigned long long kc = cand[w][s];   // LDS broadcast
#pragma unroll
            for (int m = 0; m < 2; ++m) rk[m] += (kc < my[m]) ? 1 : 0;
        }
        knn[w][lane] = -1;
        __syncwarp();
#pragma unroll
        for (int m = 0; m < 2; ++m)
            if (my[m] != ~0ull && rk[m] < kk)
                knn[w][rk[m]] = (int)(unsigned)my[m];
        __syncwarp();
    }

    // ---- write phase: warp w streams row (row0 + w) via nibble LUT ----
    {
        const int grow = row0 + w;
        const int iloc = i0 + w;

        // register nibble-bitmap: lane covers float4 groups m = it*32 + lane
        unsigned b0 = 0, b1 = 0, b2 = 0, b3 = 0;
        for (int q = 0; q < kk; ++q) {
            int j = knn[w][q];
            if (j >= 0 && ((j >> 2) & 31) == lane) {
                int it = j >> 7;
                unsigned sh = 1u << (((it & 7) << 2) | (j & 3));
                if (it < 8) b0 |= sh; else if (it < 16) b1 |= sh;
                else if (it < 24) b2 |= sh; else b3 |= sh;
            }
        }

        float4* ob = reinterpret_cast<float4*>(out) + (size_t)grow * (NN / 4) + lane;
#pragma unroll
        for (int it = 0; it < 32; ++it) {
            unsigned reg = (it < 8) ? b0 : (it < 16) ? b1 : (it < 24) ? b2 : b3;
            unsigned nib = (reg >> ((it & 7) * 4)) & 15u;
            ob[it * 32] = lut[nib];
        }
        // diagonal fixup by the same thread that wrote the containing float4
        const int dl = (iloc >> 2) & 31;
        if (lane == dl) {
            const int dit = iloc >> 7;
            unsigned reg = (dit < 8) ? b0 : (dit < 16) ? b1 : (dit < 24) ? b2 : b3;
            unsigned bit = (reg >> (((dit & 7) << 2) | (iloc & 3))) & 1u;
            out[(size_t)grow * NN + iloc] = 1.0f + (bit ? voff : 0.0f);
        }
    }
}

extern "C" void kernel_launch(void* const* d_in, const int* in_sizes, int n_in,
                              void* d_out, int out_size) {
    const float* x   = (const float*)d_in[0];
    const int*   kpt = (n_in >= 2) ? (const int*)d_in[1] : nullptr;
    float*       out = (float*)d_out;

    int total_rows = in_sizes[0] / 3;      // 16384
    int grid = total_rows / ROWS;          // 2048

    cudaFuncSetAttribute(gcn_fused,
                         cudaFuncAttributeMaxDynamicSharedMemorySize, SMEM_TOTAL);
    gcn_fused<<<grid, NT, SMEM_TOTAL>>>(x, kpt, out);
}

// round 5
// speedup vs baseline: 1.5443x; 1.0840x over previous
#include <cuda_runtime.h>
#include <cstdint>

// ---------------------------------------------------------------------------
// BaseGCN fused: kNN + Laplacian. One CTA = 4 rows, 256 threads, 4096 CTAs.
// out[g,i,j] = (j==i) - (1/k) * [j in knn(i)]   (deg == k always).
//
//  stage: points interleaved as u64-packed pairs {x01,y01,z01} (24B/group)
//  zero:  each CTA zeroes its 4 output rows immediately (STG.128 drains
//         under subsequent compute); final values scattered at the end.
//  pass1: packed f32x2 distances s01 = fma2 chains; per-thread minima for
//         4 rows, reduced to 32 group-of-8 minima (u16 ordered prefixes)
//  thr:   warp r (r<4) counting-ranks the 32 minima; rank k-1 value T
//         guarantees >= k candidates <= T  =>  top-k is in collected set
//  pass3: recompute packed s01, vote-gated collection of keys <= T (~23)
//  pass4: counting-rank of candidates -> exact top-k (64-bit (dist,idx)
//         keys => lowest-index tie-break, matching lax.top_k)
//  scatter: warp r writes ~k nonzeros + diagonal of its row
// ---------------------------------------------------------------------------

constexpr int NN   = 4096;
constexpr int ROWS = 4;
constexpr int NT   = 256;
constexpr int CAP  = 64;

// smem offsets (bytes)
constexpr int OFF_PTS  = 0;          // 2048 groups * 24B = 49152
constexpr int OFF_TM   = 49152;      // u16 tm16[4][32]     256
constexpr int OFF_CAND = 49408;      // u64 cand[4][64]    2048
constexpr int OFF_KNN  = 51456;      // int knn[4][32]      512
constexpr int OFF_MISC = 51968;      // sT16[4] cnt[4] act[4] anyf
constexpr int SMEM_TOTAL = OFF_MISC + 128;   // 52096 -> 4 CTAs/SM

using u64 = unsigned long long;

__device__ __forceinline__ u64 fma2(u64 a, u64 b, u64 c) {
    u64 d; asm("fma.rn.f32x2 %0, %1, %2, %3;" : "=l"(d) : "l"(a), "l"(b), "l"(c));
    return d;
}
__device__ __forceinline__ u64 mul2(u64 a, u64 b) {
    u64 d; asm("mul.rn.f32x2 %0, %1, %2;" : "=l"(d) : "l"(a), "l"(b));
    return d;
}
__device__ __forceinline__ u64 pack2(float a, float b) {
    u64 d; asm("mov.b64 %0, {%1, %2};" : "=l"(d) : "f"(a), "f"(b));
    return d;
}
__device__ __forceinline__ u64 splat2(float a) { return pack2(a, a); }
__device__ __forceinline__ float lo2(u64 v) { return __uint_as_float((unsigned)v); }
__device__ __forceinline__ float hi2(u64 v) { return __uint_as_float((unsigned)(v >> 32)); }

__device__ __forceinline__ unsigned f2ord(float f) {
    unsigned b = __float_as_uint(f);
    return b ^ ((b & 0x80000000u) ? 0xFFFFFFFFu : 0x80000000u);
}
__device__ __forceinline__ float ord2f(unsigned u) {
    unsigned b = (u & 0x80000000u) ? (u ^ 0x80000000u) : ~u;
    return __uint_as_float(b);
}

extern "C" __global__ void __launch_bounds__(NT, 4)
gcn_fused(const float* __restrict__ x, const int* __restrict__ kptr,
          float* __restrict__ out) {
    extern __shared__ unsigned char sm[];
    unsigned char* smp = sm + OFF_PTS;
    unsigned short (*tm16)[32] =
        reinterpret_cast<unsigned short(*)[32]>(sm + OFF_TM);
    u64 (*cand)[CAP] = reinterpret_cast<u64(*)[CAP]>(sm + OFF_CAND);
    int (*knn)[32]   = reinterpret_cast<int(*)[32]>(sm + OFF_KNN);
    unsigned* sT16 = reinterpret_cast<unsigned*>(sm + OFF_MISC);
    int*      cnt  = reinterpret_cast<int*>(sm + OFF_MISC + 16);
    int*      act  = reinterpret_cast<int*>(sm + OFF_MISC + 32);
    int*      anyf = reinterpret_cast<int*>(sm + OFF_MISC + 48);

    const int tid   = threadIdx.x;
    const int lane  = tid & 31;
    const int w     = tid >> 5;
    const int row0  = blockIdx.x * ROWS;
    const int batch = row0 >> 12;
    const int i0    = row0 & (NN - 1);
    const float* xb = x + (size_t)batch * NN * 3;

    int kk = (kptr != nullptr) ? *kptr : 20;
    kk = max(1, min(kk, 32));
    const float voff = -1.0f / (float)kk;

    // ---- staging: 12 floats (4 points) per quad, interleaved u64 pairs ----
    {
        const float4* xb4 = reinterpret_cast<const float4*>(xb);
#pragma unroll
        for (int it = 0; it < 4; ++it) {
            int m = it * NT + tid;                 // quad index 0..1023
            float4 q0 = xb4[3 * m], q1 = xb4[3 * m + 1], q2 = xb4[3 * m + 2];
            u64* g0 = reinterpret_cast<u64*>(smp + 48 * m);
            g0[0] = pack2(q0.x, q0.w);
            g0[1] = pack2(q0.y, q1.x);
            g0[2] = pack2(q0.z, q1.y);
            u64* g1 = reinterpret_cast<u64*>(smp + 48 * m + 24);
            g1[0] = pack2(q1.z, q2.y);
            g1[1] = pack2(q1.w, q2.z);
            g1[2] = pack2(q2.x, q2.w);
        }
    }
    if (tid < ROWS) act[tid] = 1;
    __syncthreads();

    // ---- per-row packed constants -2*x_i ----
    u64 PMX[ROWS], PMY[ROWS], PMZ[ROWS];
#pragma unroll
    for (int r = 0; r < ROWS; ++r) {
        int i = i0 + r;
        const u64* g = reinterpret_cast<const u64*>(smp + 24 * (i >> 1));
        int h = i & 1;
        float px = h ? hi2(g[0]) : lo2(g[0]);
        float py = h ? hi2(g[1]) : lo2(g[1]);
        float pz = h ? hi2(g[2]) : lo2(g[2]);
        PMX[r] = splat2(-2.0f * px);
        PMY[r] = splat2(-2.0f * py);
        PMZ[r] = splat2(-2.0f * pz);
    }

    // ---- zero-fill this CTA's 4 output rows (drains under compute) ----
    {
        const float4 z4 = make_float4(0.f, 0.f, 0.f, 0.f);
        float4* ob = reinterpret_cast<float4*>(out) + (size_t)row0 * (NN / 4);
#pragma unroll
        for (int it = 0; it < 16; ++it) ob[it * NT + tid] = z4;
    }

    // ---- pass 1: packed minima ----
    float tm[ROWS];
#pragma unroll
    for (int r = 0; r < ROWS; ++r) tm[r] = 3.0e38f;
    const unsigned char* pb = smp + 24 * tid;
#pragma unroll
    for (int t = 0; t < 8; ++t) {
        const u64* gp = reinterpret_cast<const u64*>(pb + t * 6144);
        u64 x01 = gp[0], y01 = gp[1], z01 = gp[2];
        u64 w01 = fma2(x01, x01, fma2(y01, y01, mul2(z01, z01)));
#pragma unroll
        for (int r = 0; r < ROWS; ++r) {
            u64 s01 = fma2(x01, PMX[r], fma2(y01, PMY[r], fma2(z01, PMZ[r], w01)));
            tm[r] = fminf(tm[r], fminf(lo2(s01), hi2(s01)));
        }
    }
    // group-of-8 minima -> u16 ordered prefixes. Group g covers threads
    // [8g, 8g+8) x 8 t-iters x 2 cands = 128 disjoint candidates.
#pragma unroll
    for (int r = 0; r < ROWS; ++r) {
        float v = tm[r];
        v = fminf(v, __shfl_down_sync(0xFFFFFFFFu, v, 4, 8));
        v = fminf(v, __shfl_down_sync(0xFFFFFFFFu, v, 2, 8));
        v = fminf(v, __shfl_down_sync(0xFFFFFFFFu, v, 1, 8));
        if ((tid & 7) == 0)
            tm16[r][tid >> 3] = (unsigned short)(f2ord(v) >> 16);
    }
    __syncthreads();

    // ---- threshold: warp r<4 counting-ranks the 32 group minima ----
    unsigned T16base = 0;
    if (w < ROWS) {
        const unsigned lm = (unsigned)tm16[w][lane];
        int c = 0;
#pragma unroll
        for (int s = 0; s < 32; ++s) {
            unsigned v = __shfl_sync(0xFFFFFFFFu, lm, s);
            c += (v < lm || (v == lm && s < lane)) ? 1 : 0;
        }
        unsigned eq = __ballot_sync(0xFFFFFFFFu, c == kk - 1);
        T16base = __shfl_sync(0xFFFFFFFFu, lm, __ffs(eq) - 1);
    }

    // ---- collection attempts (retry statistically unreachable) ----
    for (int attempt = 0; attempt < 3; ++attempt) {
        if (w < ROWS && lane == 0 && act[w]) {
            unsigned d = (unsigned)attempt;
            sT16[w] = (T16base > d) ? (T16base - d) : 0u;
            cnt[w] = 0;
        }
        __syncthreads();

        float thrf[ROWS];
#pragma unroll
        for (int r = 0; r < ROWS; ++r)
            thrf[r] = act[r] ? ord2f((sT16[r] << 16) | 0xFFFFu)
                             : __int_as_float(0xFF800000);   // -inf

        // pass 3: recompute packed s, collect keys <= T
#pragma unroll 2
        for (int t = 0; t < 8; ++t) {
            const u64* gp = reinterpret_cast<const u64*>(pb + t * 6144);
            u64 x01 = gp[0], y01 = gp[1], z01 = gp[2];
            u64 w01 = fma2(x01, x01, fma2(y01, y01, mul2(z01, z01)));
            int j0 = 2 * (t * NT + tid);
#pragma unroll
            for (int r = 0; r < ROWS; ++r) {
                u64 s01 = fma2(x01, PMX[r], fma2(y01, PMY[r], fma2(z01, PMZ[r], w01)));
                float s0 = lo2(s01), s1 = hi2(s01);
                bool hit = fminf(s0, s1) <= thrf[r];
                if (__any_sync(0xFFFFFFFFu, hit)) {
                    if (s0 <= thrf[r]) {
                        int pos = atomicAdd(&cnt[r], 1);
                        if (pos < CAP)
                            cand[r][pos] = ((u64)f2ord(s0) << 32) | (unsigned)j0;
                    }
                    if (s1 <= thrf[r]) {
                        int pos = atomicAdd(&cnt[r], 1);
                        if (pos < CAP)
                            cand[r][pos] = ((u64)f2ord(s1) << 32) | (unsigned)(j0 + 1);
                    }
                }
            }
        }
        __syncthreads();
        if (tid < ROWS) {
            if (act[tid]) act[tid] = (cnt[tid] > CAP) ? 1 : 0;
        }
        if (tid == 0) {
            int a = 0;
#pragma unroll
            for (int r = 0; r < ROWS; ++r) a |= act[r];
            *anyf = a;
        }
        __syncthreads();
        if (!*anyf) break;
    }

    // ---- pass 4 + scatter: warp r<4 owns row r ----
    if (w < ROWS) {
        const int r = w;
        const int c = min(cnt[r], CAP);
        u64 my[2];
#pragma unroll
        for (int m = 0; m < 2; ++m) {
            int pos = lane + 32 * m;
            my[m] = (pos < c) ? cand[r][pos] : ~0ull;
        }
        int rk[2] = {0, 0};
#pragma unroll 4
        for (int s = 0; s < c; ++s) {
            u64 kc = cand[r][s];                  // LDS broadcast
#pragma unroll
            for (int m = 0; m < 2; ++m) rk[m] += (kc < my[m]) ? 1 : 0;
        }
        knn[r][lane] = -1;
        __syncwarp();
#pragma unroll
        for (int m = 0; m < 2; ++m)
            if (my[m] != ~0ull && rk[m] < kk)
                knn[r][rk[m]] = (int)(unsigned)my[m];
        __syncwarp();

        // scatter nonzeros (rows already zeroed before pass1; ordering via
        // the intervening __syncthreads barriers)
        const int grow = row0 + r;
        const int iloc = i0 + r;
        float* orf = out + (size_t)grow * NN;
        int j = (lane < kk) ? knn[r][lane] : -1;
        bool selfin = (j == iloc);
        unsigned fmask = __ballot_sync(0xFFFFFFFFu, selfin);
        if (lane < kk && j >= 0)
            orf[j] = selfin ? (1.0f + voff) : voff;
        if (lane == 0 && fmask == 0u)
            orf[iloc] = 1.0f;
    }
}

extern "C" void kernel_launch(void* const* d_in, const int* in_sizes, int n_in,
                              void* d_out, int out_size) {
    const float* x   = (const float*)d_in[0];
    const int*   kpt = (n_in >= 2) ? (const int*)d_in[1] : nullptr;
    float*       out = (float*)d_out;

    int total_rows = in_sizes[0] / 3;      // 16384
    int grid = total_rows / ROWS;          // 4096

    cudaFuncSetAttribute(gcn_fused,
                         cudaFuncAttributeMaxDynamicSharedMemorySize, SMEM_TOTAL);
    gcn_fused<<<grid, NT, SMEM_TOTAL>>>(x, kpt, out);
}

// round 6
// speedup vs baseline: 1.5610x; 1.0109x over previous
#include <cuda_runtime.h>
#include <cstdint>

// ---------------------------------------------------------------------------
// BaseGCN fused: kNN + Laplacian. One CTA = 4 rows, 256 threads, 4096 CTAs.
// out[g,i,j] = (j==i) - (1/k) * [j in knn(i)]   (deg == k always).
//
//  stage: points interleaved as u64-packed pairs {x01,y01,z01} (24B/group)
//  zero:  CTA zeroes its 4 output rows early with __stcs (drains under compute)
//  pass1: packed f32x2 distances; per-thread minima for 4 rows, reduced to
//         32 group-of-8 minima (u16 ordered prefixes)
//  thr:   warp r<4 counting-ranks the 32 minima; rank k-1 value T guarantees
//         >= k candidates <= T  =>  collected set contains the exact top-k
//  fast collect: straight-line fully-unrolled recompute+gather (~23 cands)
//  retry: unreachable-in-practice fallback loop (uniform branch)
//  pass4: warps w / w+4 co-rank row w's candidates -> exact top-k
//         (64-bit (ord(dist), idx) keys => lowest-index ties, == lax.top_k)
//  scatter: warp r<4 writes ~k nonzeros + diagonal of its row
// ---------------------------------------------------------------------------

constexpr int NN   = 4096;
constexpr int ROWS = 4;
constexpr int NT   = 256;
constexpr int CAP  = 64;

// smem offsets (bytes)
constexpr int OFF_PTS  = 0;          // 2048 groups * 24B = 49152
constexpr int OFF_TM   = 49152;      // u16 tm16[4][32]     256
constexpr int OFF_CAND = 49408;      // u64 cand[4][64]    2048
constexpr int OFF_KNN  = 51456;      // int knn[4][32]      512
constexpr int OFF_MISC = 51968;      // sT16[4] cnt[4] act[4] anyf
constexpr int SMEM_TOTAL = OFF_MISC + 128;   // 52096 -> 4 CTAs/SM

using u64 = unsigned long long;

__device__ __forceinline__ u64 fma2(u64 a, u64 b, u64 c) {
    u64 d; asm("fma.rn.f32x2 %0, %1, %2, %3;" : "=l"(d) : "l"(a), "l"(b), "l"(c));
    return d;
}
__device__ __forceinline__ u64 mul2(u64 a, u64 b) {
    u64 d; asm("mul.rn.f32x2 %0, %1, %2;" : "=l"(d) : "l"(a), "l"(b));
    return d;
}
__device__ __forceinline__ u64 pack2(float a, float b) {
    u64 d; asm("mov.b64 %0, {%1, %2};" : "=l"(d) : "f"(a), "f"(b));
    return d;
}
__device__ __forceinline__ u64 splat2(float a) { return pack2(a, a); }
__device__ __forceinline__ float lo2(u64 v) { return __uint_as_float((unsigned)v); }
__device__ __forceinline__ float hi2(u64 v) { return __uint_as_float((unsigned)(v >> 32)); }

__device__ __forceinline__ unsigned f2ord(float f) {
    unsigned b = __float_as_uint(f);
    return b ^ ((b & 0x80000000u) ? 0xFFFFFFFFu : 0x80000000u);
}
__device__ __forceinline__ float ord2f(unsigned u) {
    unsigned b = (u & 0x80000000u) ? (u ^ 0x80000000u) : ~u;
    return __uint_as_float(b);
}

extern "C" __global__ void __launch_bounds__(NT, 4)
gcn_fused(const float* __restrict__ x, const int* __restrict__ kptr,
          float* __restrict__ out) {
    extern __shared__ unsigned char sm[];
    unsigned char* smp = sm + OFF_PTS;
    unsigned short (*tm16)[32] =
        reinterpret_cast<unsigned short(*)[32]>(sm + OFF_TM);
    u64 (*cand)[CAP] = reinterpret_cast<u64(*)[CAP]>(sm + OFF_CAND);
    int (*knn)[32]   = reinterpret_cast<int(*)[32]>(sm + OFF_KNN);
    unsigned* sT16 = reinterpret_cast<unsigned*>(sm + OFF_MISC);
    int*      cnt  = reinterpret_cast<int*>(sm + OFF_MISC + 16);
    int*      act  = reinterpret_cast<int*>(sm + OFF_MISC + 32);
    int*      anyf = reinterpret_cast<int*>(sm + OFF_MISC + 48);

    const int tid   = threadIdx.x;
    const int lane  = tid & 31;
    const int w     = tid >> 5;
    const int row0  = blockIdx.x * ROWS;
    const int batch = row0 >> 12;
    const int i0    = row0 & (NN - 1);
    const float* xb = x + (size_t)batch * NN * 3;

    int kk = (kptr != nullptr) ? *kptr : 20;
    kk = max(1, min(kk, 32));
    const float voff = -1.0f / (float)kk;

    // ---- staging: 12 floats (4 points) per quad, interleaved u64 pairs ----
    {
        const float4* xb4 = reinterpret_cast<const float4*>(xb);
#pragma unroll
        for (int it = 0; it < 4; ++it) {
            int m = it * NT + tid;                 // quad index 0..1023
            float4 q0 = xb4[3 * m], q1 = xb4[3 * m + 1], q2 = xb4[3 * m + 2];
            u64* g0 = reinterpret_cast<u64*>(smp + 48 * m);
            g0[0] = pack2(q0.x, q0.w);
            g0[1] = pack2(q0.y, q1.x);
            g0[2] = pack2(q0.z, q1.y);
            u64* g1 = reinterpret_cast<u64*>(smp + 48 * m + 24);
            g1[0] = pack2(q1.z, q2.y);
            g1[1] = pack2(q1.w, q2.z);
            g1[2] = pack2(q2.x, q2.w);
        }
    }
    if (tid < ROWS) { act[tid] = 1; cnt[tid] = 0; }
    __syncthreads();

    // ---- per-row packed constants -2*x_i ----
    u64 PMX[ROWS], PMY[ROWS], PMZ[ROWS];
#pragma unroll
    for (int r = 0; r < ROWS; ++r) {
        int i = i0 + r;
        const u64* g = reinterpret_cast<const u64*>(smp + 24 * (i >> 1));
        int h = i & 1;
        float px = h ? hi2(g[0]) : lo2(g[0]);
        float py = h ? hi2(g[1]) : lo2(g[1]);
        float pz = h ? hi2(g[2]) : lo2(g[2]);
        PMX[r] = splat2(-2.0f * px);
        PMY[r] = splat2(-2.0f * py);
        PMZ[r] = splat2(-2.0f * pz);
    }

    // ---- zero-fill this CTA's 4 output rows (streaming, drains under compute)
    {
        const float4 z4 = make_float4(0.f, 0.f, 0.f, 0.f);
        float4* ob = reinterpret_cast<float4*>(out) + (size_t)row0 * (NN / 4);
#pragma unroll
        for (int it = 0; it < 16; ++it) __stcs(&ob[it * NT + tid], z4);
    }

    // ---- pass 1: packed per-thread minima ----
    float tm[ROWS];
#pragma unroll
    for (int r = 0; r < ROWS; ++r) tm[r] = 3.0e38f;
    const unsigned char* pb = smp + 24 * tid;
#pragma unroll
    for (int t = 0; t < 8; ++t) {
        const u64* gp = reinterpret_cast<const u64*>(pb + t * 6144);
        u64 x01 = gp[0], y01 = gp[1], z01 = gp[2];
        u64 w01 = fma2(x01, x01, fma2(y01, y01, mul2(z01, z01)));
#pragma unroll
        for (int r = 0; r < ROWS; ++r) {
            u64 s01 = fma2(x01, PMX[r], fma2(y01, PMY[r], fma2(z01, PMZ[r], w01)));
            tm[r] = fminf(tm[r], fminf(lo2(s01), hi2(s01)));
        }
    }
    // group-of-8 minima -> u16 ordered prefixes. Group g covers threads
    // [8g, 8g+8) x 8 t-iters x 2 cands = 128 disjoint candidates.
#pragma unroll
    for (int r = 0; r < ROWS; ++r) {
        float v = tm[r];
        v = fminf(v, __shfl_down_sync(0xFFFFFFFFu, v, 4, 8));
        v = fminf(v, __shfl_down_sync(0xFFFFFFFFu, v, 2, 8));
        v = fminf(v, __shfl_down_sync(0xFFFFFFFFu, v, 1, 8));
        if ((tid & 7) == 0)
            tm16[r][tid >> 3] = (unsigned short)(f2ord(v) >> 16);
    }
    __syncthreads();

    // ---- threshold: warp r<4 counting-ranks the 32 group minima ----
    unsigned T16base = 0;
    if (w < ROWS) {
        const unsigned lm = (unsigned)tm16[w][lane];
        int c = 0;
#pragma unroll
        for (int s = 0; s < 32; ++s) {
            unsigned v = __shfl_sync(0xFFFFFFFFu, lm, s);
            c += (v < lm || (v == lm && s < lane)) ? 1 : 0;
        }
        unsigned eq = __ballot_sync(0xFFFFFFFFu, c == kk - 1);
        T16base = __shfl_sync(0xFFFFFFFFu, lm, __ffs(eq) - 1);
        if (lane == 0) sT16[w] = T16base;
        knn[w][lane] = -1;                 // init for pass4
    }
    __syncthreads();

    // ---- fast collection (attempt 0): straight-line, fully unrolled ----
    {
        float thrf[ROWS];
#pragma unroll
        for (int r = 0; r < ROWS; ++r)
            thrf[r] = ord2f((sT16[r] << 16) | 0xFFFFu);

#pragma unroll
        for (int t = 0; t < 8; ++t) {
            const u64* gp = reinterpret_cast<const u64*>(pb + t * 6144);
            u64 x01 = gp[0], y01 = gp[1], z01 = gp[2];
            u64 w01 = fma2(x01, x01, fma2(y01, y01, mul2(z01, z01)));
            int j0 = 2 * (t * NT + tid);
#pragma unroll
            for (int r = 0; r < ROWS; ++r) {
                u64 s01 = fma2(x01, PMX[r], fma2(y01, PMY[r], fma2(z01, PMZ[r], w01)));
                float s0 = lo2(s01), s1 = hi2(s01);
                bool h0 = (s0 <= thrf[r]), h1 = (s1 <= thrf[r]);
                if (__any_sync(0xFFFFFFFFu, h0 || h1)) {
                    if (h0) {
                        int pos = atomicAdd(&cnt[r], 1);
                        if (pos < CAP)
                            cand[r][pos] = ((u64)f2ord(s0) << 32) | (unsigned)j0;
                    }
                    if (h1) {
                        int pos = atomicAdd(&cnt[r], 1);
                        if (pos < CAP)
                            cand[r][pos] = ((u64)f2ord(s1) << 32) | (unsigned)(j0 + 1);
                    }
                }
            }
        }
    }
    __syncthreads();
    if (tid < ROWS) act[tid] = (cnt[tid] > CAP) ? 1 : 0;
    if (tid == 0) *anyf = 0;
    __syncthreads();
    if (tid < ROWS && act[tid]) atomicOr(anyf, 1);
    __syncthreads();

    // ---- retry fallback (statistically unreachable; uniform branch) ----
    if (__builtin_expect(*anyf, 0)) {
        for (int attempt = 1; attempt < 3; ++attempt) {
            if (w < ROWS && lane == 0 && act[w]) {
                unsigned d = (unsigned)attempt;
                sT16[w] = (T16base > d) ? (T16base - d) : 0u;
                cnt[w] = 0;
            }
            __syncthreads();
            float thrf[ROWS];
#pragma unroll
            for (int r = 0; r < ROWS; ++r)
                thrf[r] = act[r] ? ord2f((sT16[r] << 16) | 0xFFFFu)
                                 : __int_as_float(0xFF800000);   // -inf
#pragma unroll 2
            for (int t = 0; t < 8; ++t) {
                const u64* gp = reinterpret_cast<const u64*>(pb + t * 6144);
                u64 x01 = gp[0], y01 = gp[1], z01 = gp[2];
                u64 w01 = fma2(x01, x01, fma2(y01, y01, mul2(z01, z01)));
                int j0 = 2 * (t * NT + tid);
#pragma unroll
                for (int r = 0; r < ROWS; ++r) {
                    u64 s01 = fma2(x01, PMX[r], fma2(y01, PMY[r], fma2(z01, PMZ[r], w01)));
                    float s0 = lo2(s01), s1 = hi2(s01);
                    if (s0 <= thrf[r]) {
                        int pos = atomicAdd(&cnt[r], 1);
                        if (pos < CAP)
                            cand[r][pos] = ((u64)f2ord(s0) << 32) | (unsigned)j0;
                    }
                    if (s1 <= thrf[r]) {
                        int pos = atomicAdd(&cnt[r], 1);
                        if (pos < CAP)
                            cand[r][pos] = ((u64)f2ord(s1) << 32) | (unsigned)(j0 + 1);
                    }
                }
            }
            __syncthreads();
            if (tid < ROWS) {
                if (act[tid]) act[tid] = (cnt[tid] > CAP) ? 1 : 0;
            }
            if (tid == 0) {
                int a = 0;
#pragma unroll
                for (int r = 0; r < ROWS; ++r) a |= act[r];
                *anyf = a;
            }
            __syncthreads();
            if (!*anyf) break;
        }
    }

    // ---- pass 4: warps w and w+4 co-rank row (w & 3); one key per lane ----
    {
        const int r = w & 3;
        const int c = min(cnt[r], CAP);
        const int slot = lane + ((w >> 2) << 5);   // w<4: 0..31, w>=4: 32..63
        u64 my = (slot < c) ? cand[r][slot] : ~0ull;
        int rk = 0;
#pragma unroll 4
        for (int s = 0; s < c; ++s)
            rk += (cand[r][s] < my) ? 1 : 0;       // LDS broadcast
        if (my != ~0ull && rk < kk)
            knn[r][rk] = (int)(unsigned)my;
    }
    __syncthreads();

    // ---- scatter: warp r<4 writes its row's nonzeros + diagonal ----
    if (w < ROWS) {
        const int r = w;
        const int grow = row0 + r;
        const int iloc = i0 + r;
        float* orf = out + (size_t)grow * NN;
        int j = (lane < kk) ? knn[r][lane] : -1;
        bool selfin = (j == iloc);
        unsigned fmask = __ballot_sync(0xFFFFFFFFu, selfin);
        if (lane < kk && j >= 0)
            orf[j] = selfin ? (1.0f + voff) : voff;
        if (lane == 0 && fmask == 0u)
            orf[iloc] = 1.0f;
    }
}

extern "C" void kernel_launch(void* const* d_in, const int* in_sizes, int n_in,
                              void* d_out, int out_size) {
    const float* x   = (const float*)d_in[0];
    const int*   kpt = (n_in >= 2) ? (const int*)d_in[1] : nullptr;
    float*       out = (float*)d_out;

    int total_rows = in_sizes[0] / 3;      // 16384
    int grid = total_rows / ROWS;          // 4096

    cudaFuncSetAttribute(gcn_fused,
                         cudaFuncAttributeMaxDynamicSharedMemorySize, SMEM_TOTAL);
    gcn_fused<<<grid, NT, SMEM_TOTAL>>>(x, kpt, out);
}